// round 14
// baseline (speedup 1.0000x reference)
#include <cuda_runtime.h>
#include <cuda_fp16.h>
#include <cstdint>

// Correlation via mma.sync (HMMA) banded local GEMM.
// Per block: tile 16w x 4h px. Warp w = py row (16 px = m16).
// D_py[tx][wc] = sum_c d1[c, y0+py, x0+tx] * win[c, r=py+dyi, wc],  wc = tx+dxi.
// win rows r=0..11 <-> gy = y0-4+r; win cols 0..23 <-> gx = x0-4+wc. Zero pad OOB.
// fp16 split: A = (ah, al) fp16 planes, B = bh only:
//   acc += ah*bh ; acc += al*bh  ==> sum a*bh  (err = sum a*bl ~ 3e-4 rel, norm)
// out[n][q=dyi*9+dxi][y0+py][x0+tx] = D[tx][tx+dxi]/256.

#define HH 96
#define WW 160
#define CC 256
#define NN 8
#define HWSZ (HH*WW)
#define TW 16
#define TH 4
#define NTHREADS 128
#define CKCH 16
#define NCHUNK (CC/CKCH)      // 16

#define A_ROW 80              // [hi 32B][lo 32B][pad 16B]
#define A_BYTES (64*A_ROW)    // 5120
#define B_ROW 48              // [hi 32B][pad 16B]
#define B_BYTES (288*B_ROW)   // 13824  (288 win-px rows = 12 r * 24 c)
#define INVALID 0xFFFFFFFFu

static __device__ __forceinline__ uint32_t pack_h2(float e0, float e1) {
    // result: low16 = f16(e0), high16 = f16(e1)
    uint32_t r;
    asm("cvt.rn.f16x2.f32 %0, %1, %2;" : "=r"(r) : "f"(e1), "f"(e0));
    return r;
}
static __device__ __forceinline__ void h2_to_f2(uint32_t h2, float& f0, float& f1) {
    asm("{\n\t.reg .b16 l, h;\n\tmov.b32 {l, h}, %2;\n\t"
        "cvt.f32.f16 %0, l;\n\tcvt.f32.f16 %1, h;\n\t}"
        : "=f"(f0), "=f"(f1) : "r"(h2));
}
static __device__ __forceinline__ void sts32(uint32_t addr, uint32_t v) {
    asm volatile("st.shared.b32 [%0], %1;" :: "r"(addr), "r"(v));
}
static __device__ __forceinline__ void ldsm4(uint32_t* r, uint32_t a) {
    asm volatile("ldmatrix.sync.aligned.m8n8.x4.shared.b16 {%0,%1,%2,%3}, [%4];"
        : "=r"(r[0]), "=r"(r[1]), "=r"(r[2]), "=r"(r[3]) : "r"(a));
}
static __device__ __forceinline__ void ldsm2(uint32_t* r, uint32_t a) {
    asm volatile("ldmatrix.sync.aligned.m8n8.x2.shared.b16 {%0,%1}, [%2];"
        : "=r"(r[0]), "=r"(r[1]) : "r"(a));
}
static __device__ __forceinline__ void mma16816(float* d, const uint32_t* a,
                                                const uint32_t* b) {
    asm volatile(
        "mma.sync.aligned.m16n8k16.row.col.f32.f16.f16.f32 "
        "{%0,%1,%2,%3}, {%4,%5,%6,%7}, {%8,%9}, {%0,%1,%2,%3};"
        : "+f"(d[0]), "+f"(d[1]), "+f"(d[2]), "+f"(d[3])
        : "r"(a[0]), "r"(a[1]), "r"(a[2]), "r"(a[3]), "r"(b[0]), "r"(b[1]));
}

__global__ __launch_bounds__(NTHREADS)
void corr_mma_kernel(const float* __restrict__ d1,
                     const float* __restrict__ d2,
                     float* __restrict__ out)
{
    __shared__ __align__(16) unsigned char smA[A_BYTES];
    __shared__ __align__(16) unsigned char smB[B_BYTES];
    const uint32_t Ab = (uint32_t)__cvta_generic_to_shared(smA);
    const uint32_t Bb = (uint32_t)__cvta_generic_to_shared(smB);

    const int tid  = threadIdx.x;
    const int lane = tid & 31;
    const int py   = tid >> 5;          // warp id 0..3
    const int g    = lane >> 2;
    const int tig  = lane & 3;

    const int x0 = blockIdx.x * TW;
    const int y0 = blockIdx.y * TH;
    const int n  = blockIdx.z;
    const float* __restrict__ p1 = d1 + (size_t)n * CC * HWSZ;
    const float* __restrict__ p2 = d2 + (size_t)n * CC * HWSZ;

    // ---- A conversion task: ch2 = tid&7 (ch pair), p4 = tid>>3 (4-px group) ----
    const int a_ch2 = tid & 7, a_p4 = tid >> 3;
    const uint32_t a_g0 = (uint32_t)((2 * a_ch2) * HWSZ
                        + (y0 + (a_p4 >> 2)) * WW + x0 + (a_p4 & 3) * 4);
    const uint32_t a_sm = Ab + (uint32_t)(a_p4 * 4) * A_ROW + a_ch2 * 4;

    // ---- B conversion tasks: 576 double-tasks (12r x 6cq x 8ch2) -> up to 5 ----
    uint32_t b_g0[5], b_sm[5];
    #pragma unroll
    for (int i = 0; i < 5; i++) {
        const int task = tid + i * NTHREADS;
        if (task < 576) {
            const int ch2 = task & 7, rest = task >> 3;     // 0..71
            const int r = rest / 6, cq = rest - r * 6;
            const int gy = y0 - 4 + r, gx = x0 - 4 + 4 * cq;
            const bool ok = ((unsigned)gy < (unsigned)HH) && (gx >= 0) && (gx + 3 < WW);
            b_sm[i] = Bb + (uint32_t)(r * 24 + 4 * cq) * B_ROW + ch2 * 4;
            b_g0[i] = ok ? (uint32_t)((2 * ch2) * HWSZ + gy * WW + gx) : INVALID;
        } else { b_sm[i] = INVALID; b_g0[i] = INVALID; }
    }

    // ---- ldmatrix per-lane addresses (fixed across chunks) ----
    // A x4: matrices (m0-7,k0-7),(m8-15,k0-7),(m0-7,k8-15),(m8-15,k8-15)
    const uint32_t a_lm = Ab + (uint32_t)(py * 16 + (lane & 15)) * A_ROW
                        + ((lane >> 4) & 1) * 16;
    // B x2: rows r*24+8t+(lane&7), second matrix +16B (k8-15)
    const uint32_t b_lm0 = Bb + (uint32_t)(lane & 7) * B_ROW + ((lane >> 3) & 1) * 16;

    float acc[9][3][4];
    #pragma unroll
    for (int i = 0; i < 9; i++)
        #pragma unroll
        for (int t = 0; t < 3; t++)
            #pragma unroll
            for (int c = 0; c < 4; c++) acc[i][t][c] = 0.0f;

    for (int ci = 0; ci < NCHUNK; ci++) {
        const uint32_t coff = (uint32_t)ci * CKCH * HWSZ;

        // ---- A: load 2ch x 4px, split to (hi,lo) fp16, store packed ----
        {
            const float4 va = *reinterpret_cast<const float4*>(p1 + coff + a_g0);
            const float4 vb = *reinterpret_cast<const float4*>(p1 + coff + a_g0 + HWSZ);
            const float ea[4] = {va.x, va.y, va.z, va.w};
            const float eb[4] = {vb.x, vb.y, vb.z, vb.w};
            #pragma unroll
            for (int k2 = 0; k2 < 4; k2++) {
                const uint32_t hp = pack_h2(ea[k2], eb[k2]);
                float f0, f1;
                h2_to_f2(hp, f0, f1);
                const uint32_t lp = pack_h2(ea[k2] - f0, eb[k2] - f1);
                sts32(a_sm + (uint32_t)k2 * A_ROW, hp);
                sts32(a_sm + (uint32_t)k2 * A_ROW + 32, lp);
            }
        }
        // ---- B: hi plane only (zeros for OOB) ----
        #pragma unroll
        for (int i = 0; i < 5; i++) {
            if (b_sm[i] == INVALID) continue;
            float4 va, vb;
            if (b_g0[i] != INVALID) {
                va = *reinterpret_cast<const float4*>(p2 + coff + b_g0[i]);
                vb = *reinterpret_cast<const float4*>(p2 + coff + b_g0[i] + HWSZ);
            } else {
                va = make_float4(0.f, 0.f, 0.f, 0.f);
                vb = va;
            }
            const float ea[4] = {va.x, va.y, va.z, va.w};
            const float eb[4] = {vb.x, vb.y, vb.z, vb.w};
            #pragma unroll
            for (int k2 = 0; k2 < 4; k2++)
                sts32(b_sm[i] + (uint32_t)k2 * B_ROW, pack_h2(ea[k2], eb[k2]));
        }
        __syncthreads();

        // ---- frags + mma ----
        uint32_t ah[4], al[4];
        ldsm4(ah, a_lm);
        ldsm4(al, a_lm + 32);
        #pragma unroll
        for (int dyi = 0; dyi < 9; dyi++) {
            const int r = py + dyi;          // 0..11, always in range
            #pragma unroll
            for (int t = 0; t < 3; t++) {
                uint32_t b[2];
                ldsm2(b, b_lm0 + (uint32_t)(r * 24 + 8 * t) * B_ROW);
                mma16816(acc[dyi][t], ah, b);
                mma16816(acc[dyi][t], al, b);
            }
        }
        __syncthreads();
    }

    // ---- epilogue: band extraction, scalar stores ----
    const float scale = 1.0f / 256.0f;
    const int ybase = y0 + py;
    #pragma unroll
    for (int dyi = 0; dyi < 9; dyi++) {
        #pragma unroll
        for (int t = 0; t < 3; t++) {
            #pragma unroll
            for (int c = 0; c < 4; c++) {
                const int tx  = g + ((c >= 2) ? 8 : 0);
                const int col = 8 * t + 2 * tig + (c & 1);
                const int dxi = col - tx;
                if (dxi >= 0 && dxi <= 8) {
                    out[(((size_t)n * 81 + dyi * 9 + dxi) * HH + ybase) * WW + x0 + tx]
                        = acc[dyi][t][c] * scale;
                }
            }
        }
    }
}

extern "C" void kernel_launch(void* const* d_in, const int* in_sizes, int n_in,
                              void* d_out, int out_size)
{
    const float* d1 = (const float*)d_in[0];
    const float* d2 = (const float*)d_in[1];
    float* out = (float*)d_out;

    dim3 grid(WW / TW, HH / TH, NN);   // (10, 24, 8) = 1920 blocks
    corr_mma_kernel<<<grid, NTHREADS>>>(d1, d2, out);
}

// round 16
// speedup vs baseline: 1.4036x; 1.4036x over previous
#include <cuda_runtime.h>
#include <cuda_fp16.h>
#include <cstdint>

// Correlation via mma.sync (HMMA) banded local GEMM + cp.async staged pipeline.
// Per block: tile 16w x 4h px. Warp = py (m16 = 16 px of row py).
// D_py[tx][wc] = sum_c d1[c,y0+py,x0+tx] * win[c, r=py+dyi, wc], wc = tx+dxi.
// fp16 split: A=(ah,al), B=bh only: acc += ah*bh + al*bh  (rel err ~2e-4).
// out[n][q=dyi*9+dxi][y0+py][x0+tx] = D[tx][tx+dxi]/256.

#define HH 96
#define WW 160
#define CC 256
#define NN 8
#define HWSZ (HH*WW)
#define TW 16
#define TH 4
#define NTHREADS 128
#define CKCH 16
#define NCHUNK 16

// fp16 operand buffers
#define A_ROW 80               // [hi 32B][lo 32B][pad 16B]
#define AFP_BYTES (64*A_ROW)   // 5120
#define B_ROW 48               // [hi 32B][pad 16B]
#define BFP_OFF AFP_BYTES
#define BFP_BYTES (288*B_ROW)  // 13824 (12 r * 24 c rows)
// fp32 staging (cp.async target), 2 stages
#define ASTG_OFF 18944
#define A_CHS 68               // floats per channel (64 px + 4 pad)
#define ASTG_STAGE (16*A_CHS*4)    // 4352 B
#define BSTG_OFF (ASTG_OFF + 2*ASTG_STAGE)   // 27648
#define B_RS 28                // floats per win row (24 + 4 pad)
#define B_CHS 340              // floats per channel (12*28 + 4 pad)
#define BSTG_STAGE (16*B_CHS*4)    // 21760 B
#define SMEM_BYTES (BSTG_OFF + 2*BSTG_STAGE) // 71168

#define INVALID 0xFFFFFFFFu
// task = (src_elem_offset << 13) | dst_word_offset   (src<2^18, dst<2^13)

static __device__ __forceinline__ uint32_t pack_h2(float e0, float e1) {
    uint32_t r;  // low16 = f16(e0), high16 = f16(e1)
    asm("cvt.rn.f16x2.f32 %0, %1, %2;" : "=r"(r) : "f"(e1), "f"(e0));
    return r;
}
static __device__ __forceinline__ void h2_to_f2(uint32_t h2, float& f0, float& f1) {
    asm("{\n\t.reg .b16 l, h;\n\tmov.b32 {l, h}, %2;\n\t"
        "cvt.f32.f16 %0, l;\n\tcvt.f32.f16 %1, h;\n\t}"
        : "=f"(f0), "=f"(f1) : "r"(h2));
}
static __device__ __forceinline__ void sts32(uint32_t addr, uint32_t v) {
    asm volatile("st.shared.b32 [%0], %1;" :: "r"(addr), "r"(v));
}
static __device__ __forceinline__ void cp_async16(uint32_t dst, const float* src) {
    asm volatile("cp.async.cg.shared.global [%0], [%1], 16;\n" :: "r"(dst), "l"(src));
}
static __device__ __forceinline__ void cp_commit() {
    asm volatile("cp.async.commit_group;\n" ::: "memory");
}
static __device__ __forceinline__ void cp_wait0() {
    asm volatile("cp.async.wait_group 0;\n" ::: "memory");
}
static __device__ __forceinline__ void issue_task(uint32_t task, uint32_t sbase,
                                                  const float* gbase) {
    if (task != INVALID)
        cp_async16(sbase + ((task & 0x1FFFu) << 2), gbase + (task >> 13));
}
static __device__ __forceinline__ void ldsm4(uint32_t* r, uint32_t a) {
    asm volatile("ldmatrix.sync.aligned.m8n8.x4.shared.b16 {%0,%1,%2,%3}, [%4];"
        : "=r"(r[0]), "=r"(r[1]), "=r"(r[2]), "=r"(r[3]) : "r"(a));
}
static __device__ __forceinline__ void ldsm2(uint32_t* r, uint32_t a) {
    asm volatile("ldmatrix.sync.aligned.m8n8.x2.shared.b16 {%0,%1}, [%2];"
        : "=r"(r[0]), "=r"(r[1]) : "r"(a));
}
static __device__ __forceinline__ void mma16816(float* d, const uint32_t* a,
                                                const uint32_t* b) {
    asm volatile(
        "mma.sync.aligned.m16n8k16.row.col.f32.f16.f16.f32 "
        "{%0,%1,%2,%3}, {%4,%5,%6,%7}, {%8,%9}, {%0,%1,%2,%3};"
        : "+f"(d[0]), "+f"(d[1]), "+f"(d[2]), "+f"(d[3])
        : "r"(a[0]), "r"(a[1]), "r"(a[2]), "r"(a[3]), "r"(b[0]), "r"(b[1]));
}

__global__ __launch_bounds__(NTHREADS)
void corr_mma_kernel(const float* __restrict__ d1,
                     const float* __restrict__ d2,
                     float* __restrict__ out)
{
    extern __shared__ __align__(16) unsigned char smem_raw[];
    const uint32_t sb = (uint32_t)__cvta_generic_to_shared(smem_raw);
    const uint32_t Ab = sb;              // A fp16
    const uint32_t Bb = sb + BFP_OFF;    // B fp16
    float* const astg_gen = reinterpret_cast<float*>(smem_raw + ASTG_OFF);
    float* const bstg_gen = reinterpret_cast<float*>(smem_raw + BSTG_OFF);

    const int tid  = threadIdx.x;
    const int lane = tid & 31;
    const int py   = tid >> 5;
    const int g    = lane >> 2;
    const int tig  = lane & 3;

    const int x0 = blockIdx.x * TW;
    const int y0 = blockIdx.y * TH;
    const int n  = blockIdx.z;
    const float* __restrict__ p1 = d1 + (size_t)n * CC * HWSZ;
    const float* __restrict__ p2 = d2 + (size_t)n * CC * HWSZ;

    // ---- zero B staging (both stages): OOB slots stay zero forever ----
    {
        float4 z = make_float4(0.f, 0.f, 0.f, 0.f);
        float4* bz = reinterpret_cast<float4*>(bstg_gen);
        for (int i = tid; i < (2 * BSTG_STAGE) / 16; i += NTHREADS) bz[i] = z;
    }

    // ---- cp.async task lists (packed; offsets relative to chunk base) ----
    // A: 256 f4 tasks -> 2/thread.  stg dst: ch*A_CHS + 4*rem
    uint32_t tA[2];
    #pragma unroll
    for (int i = 0; i < 2; i++) {
        const int t = tid + i * NTHREADS;
        const int ch = t >> 4, rem = t & 15;
        const uint32_t src = (uint32_t)(ch * HWSZ + (y0 + (rem >> 2)) * WW
                                        + x0 + 4 * (rem & 3));
        const uint32_t dst = (uint32_t)(ch * A_CHS + 4 * rem);
        tA[i] = (src << 13) | dst;
    }
    // B: 1152 f4 tasks -> 9/thread.  stg dst: ch*B_CHS + r*B_RS + 4*cq
    uint32_t tB[9];
    #pragma unroll
    for (int i = 0; i < 9; i++) {
        const int t = tid + i * NTHREADS;
        const int ch = t / 72, rem = t - ch * 72;
        const int r = rem / 6, cq = rem - r * 6;
        const int gy = y0 - 4 + r, gx = x0 - 4 + 4 * cq;
        const bool ok = ((unsigned)gy < (unsigned)HH) && (gx >= 0) && (gx + 3 < WW);
        if (ok) {
            const uint32_t src = (uint32_t)(ch * HWSZ + gy * WW + gx);
            const uint32_t dst = (uint32_t)(ch * B_CHS + r * B_RS + 4 * cq);
            tB[i] = (src << 13) | dst;
        } else tB[i] = INVALID;
    }

    // ---- conversion-task constants ----
    const int a_ch2 = tid & 7, a_p4 = tid >> 3;          // A: px0 = 4*a_p4
    const uint32_t a_sm = Ab + (uint32_t)(a_p4 * 4) * A_ROW + a_ch2 * 4;
    // B conv: 576 tasks -> 5/thread (last partial)
    // task: ch2 = t&7, rest = t>>3 (0..71): r = rest/6, cq = rest%6

    // ---- ldmatrix lane addresses ----
    const uint32_t a_lm = Ab + (uint32_t)(py * 16 + (lane & 15)) * A_ROW
                        + ((lane >> 4) & 1) * 16;
    const uint32_t b_lm0 = Bb + (uint32_t)(lane & 7) * B_ROW + ((lane >> 3) & 1) * 16;

    float acc[9][3][4];
    #pragma unroll
    for (int i = 0; i < 9; i++)
        #pragma unroll
        for (int t = 0; t < 3; t++)
            #pragma unroll
            for (int c = 0; c < 4; c++) acc[i][t][c] = 0.0f;

    // zero-init visible before any cp.async writes land
    __syncthreads();

    // ---- prologue: chunk 0 -> stage 0 ----
    {
        const uint32_t As = sb + ASTG_OFF;
        const uint32_t Bs = sb + BSTG_OFF;
        #pragma unroll
        for (int i = 0; i < 2; i++) issue_task(tA[i], As, p1);
        #pragma unroll
        for (int i = 0; i < 9; i++) issue_task(tB[i], Bs, p2);
        cp_commit();
    }

    for (int ci = 0; ci < NCHUNK; ci++) {
        cp_wait0();        // my copies for chunk ci complete
        __syncthreads();   // everyone's copies visible; mma(ci-1) done (bufs free)

        // issue chunk ci+1 into the other stage (flies under convert+mma of ci)
        if (ci + 1 < NCHUNK) {
            const uint32_t coff = (uint32_t)(ci + 1) * CKCH * HWSZ;
            const int st = (ci + 1) & 1;
            const uint32_t As = sb + ASTG_OFF + st * ASTG_STAGE;
            const uint32_t Bs = sb + BSTG_OFF + st * BSTG_STAGE;
            #pragma unroll
            for (int i = 0; i < 2; i++) issue_task(tA[i], As, p1 + coff);
            #pragma unroll
            for (int i = 0; i < 9; i++) issue_task(tB[i], Bs, p2 + coff);
        }
        cp_commit();

        // ---- convert chunk ci: staging (fp32) -> fp16 operand buffers ----
        const float* astg = astg_gen + (ci & 1) * (ASTG_STAGE / 4);
        const float* bstg = bstg_gen + (ci & 1) * (BSTG_STAGE / 4);

        {   // A: 2 channels x 4 px, hi+lo split
            const float* ap = astg + 2 * a_ch2 * A_CHS + 4 * a_p4;
            const float4 va = *reinterpret_cast<const float4*>(ap);
            const float4 vb = *reinterpret_cast<const float4*>(ap + A_CHS);
            const float ea[4] = {va.x, va.y, va.z, va.w};
            const float eb[4] = {vb.x, vb.y, vb.z, vb.w};
            #pragma unroll
            for (int k2 = 0; k2 < 4; k2++) {
                const uint32_t hp = pack_h2(ea[k2], eb[k2]);
                float f0, f1;
                h2_to_f2(hp, f0, f1);
                const uint32_t lp = pack_h2(ea[k2] - f0, eb[k2] - f1);
                sts32(a_sm + (uint32_t)k2 * A_ROW, hp);
                sts32(a_sm + (uint32_t)k2 * A_ROW + 32, lp);
            }
        }
        #pragma unroll
        for (int i = 0; i < 5; i++) {   // B: hi plane only
            const int t = tid + i * NTHREADS;
            if (t >= 576) break;
            const int ch2 = t & 7, rest = t >> 3;
            const int r = rest / 6, cq = rest - r * 6;
            const float* bp = bstg + 2 * ch2 * B_CHS + r * B_RS + 4 * cq;
            const float4 va = *reinterpret_cast<const float4*>(bp);
            const float4 vb = *reinterpret_cast<const float4*>(bp + B_CHS);
            const float ea[4] = {va.x, va.y, va.z, va.w};
            const float eb[4] = {vb.x, vb.y, vb.z, vb.w};
            const uint32_t bsm = Bb + (uint32_t)(r * 24 + 4 * cq) * B_ROW + ch2 * 4;
            #pragma unroll
            for (int k2 = 0; k2 < 4; k2++)
                sts32(bsm + (uint32_t)k2 * B_ROW, pack_h2(ea[k2], eb[k2]));
        }
        __syncthreads();   // fp16 buffers ready

        // ---- frags + mma ----
        uint32_t ah[4], al[4];
        ldsm4(ah, a_lm);
        ldsm4(al, a_lm + 32);
        #pragma unroll
        for (int dyi = 0; dyi < 9; dyi++) {
            const int r = py + dyi;          // 0..11
            #pragma unroll
            for (int t = 0; t < 3; t++) {
                uint32_t b[2];
                ldsm2(b, b_lm0 + (uint32_t)(r * 24 + 8 * t) * B_ROW);
                mma16816(acc[dyi][t], ah, b);
                mma16816(acc[dyi][t], al, b);
            }
        }
    }

    // ---- epilogue: band extraction ----
    const float scale = 1.0f / 256.0f;
    const int ybase = y0 + py;
    #pragma unroll
    for (int dyi = 0; dyi < 9; dyi++) {
        #pragma unroll
        for (int t = 0; t < 3; t++) {
            #pragma unroll
            for (int c = 0; c < 4; c++) {
                const int tx  = g + ((c >= 2) ? 8 : 0);
                const int col = 8 * t + 2 * tig + (c & 1);
                const int dxi = col - tx;
                if (dxi >= 0 && dxi <= 8) {
                    out[(((size_t)n * 81 + dyi * 9 + dxi) * HH + ybase) * WW + x0 + tx]
                        = acc[dyi][t][c] * scale;
                }
            }
        }
    }
}

extern "C" void kernel_launch(void* const* d_in, const int* in_sizes, int n_in,
                              void* d_out, int out_size)
{
    const float* d1 = (const float*)d_in[0];
    const float* d2 = (const float*)d_in[1];
    float* out = (float*)d_out;

    cudaFuncSetAttribute(corr_mma_kernel,
                         cudaFuncAttributeMaxDynamicSharedMemorySize, SMEM_BYTES);

    dim3 grid(WW / TW, HH / TH, NN);   // (10, 24, 8)
    corr_mma_kernel<<<grid, NTHREADS, SMEM_BYTES>>>(d1, d2, out);
}